// round 15
// baseline (speedup 1.0000x reference)
#include <cuda_runtime.h>
#include <cuda_bf16.h>
#include <cstdint>

// CumulativeNormalizer: x [32, 512, 4000] fp32.
// out[b,f,t] = (x[t] - mean(x[0..t])) / sqrt(var(x[0..t]) + 1e-4)
//
// One 128-thread block per row; 16000B swizzled smem (14 blocks/SM).
// KEY CHANGE vs R14: each thread cp.async-stages ITS OWN 32-float segment
// (one 128B line) and waits only on its own group — no block-wide barrier
// between load and totals. First block rendezvous is the tiny cross-warp
// (S,Q) exchange, placed after per-warp compute, so slow loads overlap
// fast warps' work. Barriers: 3 -> 2.
// Identity: out = (x*c - S) * rsqrt(c*Q - S^2 + eps*c^2)  -> 1 MUFU/elem.

#define FRAMES  4000
#define ROWS    (32 * 512)
#define EPS     1e-4f
#define THREADS 128
#define SEG     32
#define ACTIVE  125                  // 125 * 32 = 4000
#define VEC4    (FRAMES / 4)         // 1000 float4 per row
#define NWARPS  4

// Swizzle in float4 units: XOR the 16B-bank column with bits [5:3].
__device__ __forceinline__ int swz4(int i4) { return i4 ^ ((i4 >> 3) & 7); }

__global__ __launch_bounds__(THREADS, 14)
void cumnorm_kernel(const float* __restrict__ x, float* __restrict__ out) {
    __shared__ float4 sd[VEC4];      // 16000 B exactly
    __shared__ float swS[NWARPS];
    __shared__ float swQ[NWARPS];

    const int tid  = threadIdx.x;
    const int lane = tid & 31;
    const int w    = tid >> 5;
    const int row  = blockIdx.x;

    const float* __restrict__ xr = x   + (size_t)row * FRAMES;
    float*       __restrict__ yr = out + (size_t)row * FRAMES;
    const float4* __restrict__ xr4 = reinterpret_cast<const float4*>(xr);

    // ---- Stage OWN segment -> shared (one 128B line per thread) ----
    const unsigned sbase = (unsigned)__cvta_generic_to_shared(sd);
    const int s4 = tid * 8;          // first float4 of this thread's segment
    if (tid < ACTIVE) {
        #pragma unroll
        for (int j = 0; j < 8; j++) {
            const unsigned dst = sbase + (unsigned)(swz4(s4 + j) * 16);
            asm volatile("cp.async.cg.shared.global [%0], [%1], 16;\n"
                         :: "r"(dst), "l"(xr4 + s4 + j));
        }
    }
    asm volatile("cp.async.commit_group;\n");
    asm volatile("cp.async.wait_group 0;\n");   // waits for OWN line only

    // ---- Per-thread segment totals (S,Q) over own 32 frames (no barrier) ----
    float S = 0.f, Q = 0.f;
    if (tid < ACTIVE) {
        #pragma unroll
        for (int j = 0; j < 8; j++) {
            const float4 v = sd[swz4(s4 + j)];
            S += v.x + v.y + v.z + v.w;
            Q = fmaf(v.x, v.x, Q);
            Q = fmaf(v.y, v.y, Q);
            Q = fmaf(v.z, v.z, Q);
            Q = fmaf(v.w, v.w, Q);
        }
    }

    // ---- Warp inclusive scan over segment totals ----
    const unsigned FULL = 0xFFFFFFFFu;
    float is = S, iq = Q;
    #pragma unroll
    for (int off = 1; off < 32; off <<= 1) {
        const float ts = __shfl_up_sync(FULL, is, off);
        const float tq = __shfl_up_sync(FULL, iq, off);
        if (lane >= off) { is += ts; iq += tq; }
    }
    if (lane == 31) { swS[w] = is; swQ[w] = iq; }
    __syncthreads();                 // first block-wide rendezvous (tiny data)

    // ---- Cross-warp exclusive offset (4 warps, broadcast reads) ----
    float offS = 0.f, offQ = 0.f;
    #pragma unroll
    for (int ww = 0; ww < NWARPS - 1; ww++) {
        if (ww < w) { offS += swS[ww]; offQ += swQ[ww]; }
    }
    const float baseS = offS + (is - S);   // exclusive prefix before segment
    const float baseQ = offQ + (iq - Q);

    // ---- Epilogue: accumulate inside own segment, normalize in place ----
    if (tid < ACTIVE) {
        float s = baseS, q = baseQ;
        float c = (float)(tid * SEG + 1);
        #pragma unroll
        for (int j = 0; j < 8; j++) {
            const int p = swz4(s4 + j);
            const float4 v = sd[p];
            float4 o;
            {   s += v.x; q = fmaf(v.x, v.x, q);
                float t = fmaf(c, q, -s * s); t = fmaf(EPS * c, c, t);
                o.x = fmaf(v.x, c, -s) * rsqrtf(t); c += 1.0f; }
            {   s += v.y; q = fmaf(v.y, v.y, q);
                float t = fmaf(c, q, -s * s); t = fmaf(EPS * c, c, t);
                o.y = fmaf(v.y, c, -s) * rsqrtf(t); c += 1.0f; }
            {   s += v.z; q = fmaf(v.z, v.z, q);
                float t = fmaf(c, q, -s * s); t = fmaf(EPS * c, c, t);
                o.z = fmaf(v.z, c, -s) * rsqrtf(t); c += 1.0f; }
            {   s += v.w; q = fmaf(v.w, v.w, q);
                float t = fmaf(c, q, -s * s); t = fmaf(EPS * c, c, t);
                o.w = fmaf(v.w, c, -s) * rsqrtf(t); c += 1.0f; }
            sd[p] = o;                      // own slots only
        }
    }
    __syncthreads();                 // epilogue writes -> unstage reads

    // ---- Unstage: shared -> global, coalesced streaming stores ----
    #pragma unroll
    for (int k = 0; k < 8; k++) {
        const int i4 = tid + THREADS * k;
        if (i4 < VEC4) {
            const float4 v = sd[swz4(i4)];
            __stcs(reinterpret_cast<float4*>(yr + i4 * 4), v);
        }
    }
}

extern "C" void kernel_launch(void* const* d_in, const int* in_sizes, int n_in,
                              void* d_out, int out_size) {
    const float* x = (const float*)d_in[0];
    float* out = (float*)d_out;
    (void)in_sizes; (void)n_in; (void)out_size;

    cumnorm_kernel<<<ROWS, THREADS>>>(x, out);   // one block per row
}